// round 1
// baseline (speedup 1.0000x reference)
#include <cuda_runtime.h>
#include <cuda_bf16.h>

// NeuralODE: h_{n+1} = h_n + 0.1 * tanh(h_n @ W[k]^T + b[k]),  k = n/10, n = 0..99
// B = D = 1024.  Output layout (tuple order): [features (1024*1024)] [traj (101*1024*1024)]
// Strategy: run the recurrence in place inside d_out's traj region.
//   traj[0] = x  (memcpy D2D)
//   step n: read traj[n], write traj[n+1]
//   features = traj[100] (memcpy D2D)

#define D_DIM 1024
#define BM 128
#define BN 64
#define BK 16
#define TM 8
#define TN 4

__global__ __launch_bounds__(256, 2)
void ode_step_kernel(const float* __restrict__ H,
                     const float* __restrict__ Wk,
                     const float* __restrict__ bk,
                     float* __restrict__ Hout)
{
    __shared__ float As[BK][BM];   // A tile, k-major-transposed:  As[k][m]
    __shared__ float Ws[BK][BN];   // W tile, k-major-transposed:  Ws[k][n]

    const int tid = threadIdx.x;
    const int bm  = blockIdx.y * BM;
    const int bn  = blockIdx.x * BN;

    float acc[TM][TN];
#pragma unroll
    for (int i = 0; i < TM; i++)
#pragma unroll
        for (int j = 0; j < TN; j++) acc[i][j] = 0.0f;

    const int ty = tid >> 4;   // 0..15 -> 8 rows each
    const int tx = tid & 15;   // 0..15 -> 4 cols each

    for (int k0 = 0; k0 < D_DIM; k0 += BK) {
        // ---- load A (H) tile: 128 rows x 16 k, 512 float4, 2 per thread ----
#pragma unroll
        for (int i = 0; i < 2; i++) {
            int idx = tid * 2 + i;          // 0..511
            int r   = idx >> 2;             // 0..127 row within tile
            int c4  = idx & 3;              // which float4 in the 16-wide k strip
            float4 v = *reinterpret_cast<const float4*>(
                &H[(size_t)(bm + r) * D_DIM + k0 + c4 * 4]);
            As[c4 * 4 + 0][r] = v.x;
            As[c4 * 4 + 1][r] = v.y;
            As[c4 * 4 + 2][r] = v.z;
            As[c4 * 4 + 3][r] = v.w;
        }
        // ---- load W tile: 64 rows(j) x 16 k, 256 float4, 1 per thread ----
        {
            int r  = tid >> 2;              // 0..63
            int c4 = tid & 3;
            float4 v = *reinterpret_cast<const float4*>(
                &Wk[(size_t)(bn + r) * D_DIM + k0 + c4 * 4]);
            Ws[c4 * 4 + 0][r] = v.x;
            Ws[c4 * 4 + 1][r] = v.y;
            Ws[c4 * 4 + 2][r] = v.z;
            Ws[c4 * 4 + 3][r] = v.w;
        }
        __syncthreads();

#pragma unroll
        for (int kk = 0; kk < BK; kk++) {
            float a[TM], w[TN];
#pragma unroll
            for (int i = 0; i < TM; i++) a[i] = As[kk][ty * TM + i];
#pragma unroll
            for (int j = 0; j < TN; j++) w[j] = Ws[kk][tx * TN + j];
#pragma unroll
            for (int i = 0; i < TM; i++)
#pragma unroll
                for (int j = 0; j < TN; j++)
                    acc[i][j] = fmaf(a[i], w[j], acc[i][j]);
        }
        __syncthreads();
    }

    // ---- epilogue: h + dt * tanh(acc + b) ----
#pragma unroll
    for (int i = 0; i < TM; i++) {
        int m = bm + ty * TM + i;
        const float* hrow = &H[(size_t)m * D_DIM];
        float* orow = &Hout[(size_t)m * D_DIM];
#pragma unroll
        for (int j = 0; j < TN; j++) {
            int n = bn + tx * TN + j;
            float f = tanhf(acc[i][j] + __ldg(&bk[n]));
            orow[n] = hrow[n] + 0.1f * f;
        }
    }
}

extern "C" void kernel_launch(void* const* d_in, const int* in_sizes, int n_in,
                              void* d_out, int out_size)
{
    (void)in_sizes; (void)n_in; (void)out_size;
    const float* x = (const float*)d_in[0];   // [1024, 1024]
    const float* W = (const float*)d_in[1];   // [10, 1024, 1024]
    const float* b = (const float*)d_in[2];   // [10, 1024]

    float* out  = (float*)d_out;
    const size_t BD = (size_t)D_DIM * D_DIM;  // 1024*1024
    float* feat = out;                         // [1024,1024]
    float* traj = out + BD;                    // [101,1024,1024]

    // traj[0] = x
    cudaMemcpyAsync(traj, x, BD * sizeof(float), cudaMemcpyDeviceToDevice, 0);

    dim3 grid(D_DIM / BN, D_DIM / BM);   // (16, 8) = 128 CTAs
    dim3 block(256);

    for (int n = 0; n < 100; n++) {
        int k = n / 10;
        ode_step_kernel<<<grid, block, 0, 0>>>(
            traj + (size_t)n * BD,
            W + (size_t)k * BD,
            b + (size_t)k * D_DIM,
            traj + (size_t)(n + 1) * BD);
    }

    // features = traj[100]
    cudaMemcpyAsync(feat, traj + (size_t)100 * BD, BD * sizeof(float),
                    cudaMemcpyDeviceToDevice, 0);
}

// round 3
// speedup vs baseline: 2.1553x; 2.1553x over previous
#include <cuda_runtime.h>
#include <cstdint>
#include <math.h>

// NeuralODE via legacy tensor-core path (mma.sync m16n8k8 tf32) — the tcgen05
// ISA is 'a'-suffix gated and this build targets plain sm_103.
// h_{n+1} = h_n + 0.1 * tanh(h_n @ W[k]^T + b[k]), k = n/10, n = 0..99, B=D=1024.
// Output: [features 1024*1024][traj 101*1024*1024]; recurrence runs in place in traj.

#define D_DIM   1024
#define BM      128
#define BN      64
#define BK      32
#define THREADS 256
#define N_STAGES (D_DIM / BK)   // 32

// SMEM row stride (in 4B words): 36 -> bank = (4*row + col) mod 32, conflict-free
// for both the STS.128 fill pattern and the per-fragment LDS.32 pattern.
#define ASTR 36
#define BSTR 36
#define A_TILE (BM * ASTR)            // 4608 words
#define B_TILE (BN * BSTR)            // 2304 words
#define SMEM_WORDS (2 * (A_TILE + B_TILE))
#define SMEM_BYTES (SMEM_WORDS * 4)   // 55296 B

__device__ __forceinline__ uint32_t f2tf32(float f) {
    uint32_t r;
    asm("cvt.rna.tf32.f32 %0, %1;" : "=r"(r) : "f"(f));
    return r;
}

__device__ __forceinline__ void mma_tf32(float c[4],
                                         uint32_t a0, uint32_t a1,
                                         uint32_t a2, uint32_t a3,
                                         uint32_t b0, uint32_t b1) {
    asm volatile(
        "mma.sync.aligned.m16n8k8.row.col.f32.tf32.tf32.f32 "
        "{%0,%1,%2,%3}, {%4,%5,%6,%7}, {%8,%9}, {%0,%1,%2,%3};"
        : "+f"(c[0]), "+f"(c[1]), "+f"(c[2]), "+f"(c[3])
        : "r"(a0), "r"(a1), "r"(a2), "r"(a3), "r"(b0), "r"(b1));
}

__global__ __launch_bounds__(THREADS, 1)
void ode_step_mma(const float* __restrict__ H,
                  const float* __restrict__ Wk,
                  const float* __restrict__ bk,
                  float* __restrict__ Hout)
{
    extern __shared__ uint32_t smem[];
    uint32_t* Asm[2] = { smem, smem + A_TILE };
    uint32_t* Bsm[2] = { smem + 2 * A_TILE, smem + 2 * A_TILE + B_TILE };

    const int tid = threadIdx.x;
    const int wid = tid >> 5;
    const int lane = tid & 31;
    const int g = lane >> 2;      // group id 0..7
    const int tig = lane & 3;     // thread in group 0..3
    const int wm = wid & 3;       // warp M index (4 x 32 rows)
    const int wn = wid >> 2;      // warp N index (2 x 32 cols)
    const int bm = blockIdx.y * BM;
    const int bn = blockIdx.x * BN;

    // prefetch registers
    float4 av[4], bv[2];

    // ---- helpers as lambdas ----
    auto load_global = [&](int s) {
#pragma unroll
        for (int i = 0; i < 4; i++) {
            int idx = tid + i * THREADS;           // 0..1023
            int r = idx >> 3, c4 = idx & 7;
            av[i] = *reinterpret_cast<const float4*>(
                &H[(size_t)(bm + r) * D_DIM + s * BK + c4 * 4]);
        }
#pragma unroll
        for (int i = 0; i < 2; i++) {
            int idx = tid + i * THREADS;           // 0..511
            int r = idx >> 3, c4 = idx & 7;
            bv[i] = *reinterpret_cast<const float4*>(
                &Wk[(size_t)(bn + r) * D_DIM + s * BK + c4 * 4]);
        }
    };

    auto store_smem = [&](int buf) {
#pragma unroll
        for (int i = 0; i < 4; i++) {
            int idx = tid + i * THREADS;
            int r = idx >> 3, c4 = idx & 7;
            uint4 u;
            u.x = f2tf32(av[i].x); u.y = f2tf32(av[i].y);
            u.z = f2tf32(av[i].z); u.w = f2tf32(av[i].w);
            *reinterpret_cast<uint4*>(&Asm[buf][r * ASTR + c4 * 4]) = u;
        }
#pragma unroll
        for (int i = 0; i < 2; i++) {
            int idx = tid + i * THREADS;
            int r = idx >> 3, c4 = idx & 7;
            uint4 u;
            u.x = f2tf32(bv[i].x); u.y = f2tf32(bv[i].y);
            u.z = f2tf32(bv[i].z); u.w = f2tf32(bv[i].w);
            *reinterpret_cast<uint4*>(&Bsm[buf][r * BSTR + c4 * 4]) = u;
        }
    };

    float acc[2][4][4];
#pragma unroll
    for (int mt = 0; mt < 2; mt++)
#pragma unroll
        for (int nt = 0; nt < 4; nt++)
#pragma unroll
            for (int r = 0; r < 4; r++) acc[mt][nt][r] = 0.0f;

    // ---- prologue ----
    load_global(0);
    store_smem(0);
    __syncthreads();

    const int mrow = wm * 32;
    const int ncol = wn * 32;

    for (int s = 0; s < N_STAGES; s++) {
        const int buf = s & 1;
        if (s + 1 < N_STAGES) load_global(s + 1);

        const uint32_t* A = Asm[buf];
        const uint32_t* B = Bsm[buf];
#pragma unroll
        for (int kk = 0; kk < 4; kk++) {
            const int k8 = kk * 8;
            uint32_t a[2][4], b[4][2];
#pragma unroll
            for (int mt = 0; mt < 2; mt++) {
                const int mb = mrow + mt * 16;
                a[mt][0] = A[(mb + g)     * ASTR + k8 + tig];
                a[mt][1] = A[(mb + g + 8) * ASTR + k8 + tig];
                a[mt][2] = A[(mb + g)     * ASTR + k8 + tig + 4];
                a[mt][3] = A[(mb + g + 8) * ASTR + k8 + tig + 4];
            }
#pragma unroll
            for (int nt = 0; nt < 4; nt++) {
                const int nb = ncol + nt * 8;
                b[nt][0] = B[(nb + g) * BSTR + k8 + tig];
                b[nt][1] = B[(nb + g) * BSTR + k8 + tig + 4];
            }
#pragma unroll
            for (int mt = 0; mt < 2; mt++)
#pragma unroll
                for (int nt = 0; nt < 4; nt++)
                    mma_tf32(acc[mt][nt],
                             a[mt][0], a[mt][1], a[mt][2], a[mt][3],
                             b[nt][0], b[nt][1]);
        }

        __syncthreads();
        if (s + 1 < N_STAGES) {
            store_smem((s + 1) & 1);
            __syncthreads();
        }
    }

    // ---- fused epilogue: h + 0.1 * tanh(acc + b) ----
#pragma unroll
    for (int mt = 0; mt < 2; mt++) {
        const int m0 = bm + mrow + mt * 16 + g;
        const int m1 = m0 + 8;
#pragma unroll
        for (int nt = 0; nt < 4; nt++) {
            const int col = bn + ncol + nt * 8 + tig * 2;
            const float b0 = __ldg(&bk[col]);
            const float b1 = __ldg(&bk[col + 1]);

            float2 h0 = *reinterpret_cast<const float2*>(&H[(size_t)m0 * D_DIM + col]);
            float2 h1 = *reinterpret_cast<const float2*>(&H[(size_t)m1 * D_DIM + col]);
            float2 o0, o1;
            o0.x = h0.x + 0.1f * tanhf(acc[mt][nt][0] + b0);
            o0.y = h0.y + 0.1f * tanhf(acc[mt][nt][1] + b1);
            o1.x = h1.x + 0.1f * tanhf(acc[mt][nt][2] + b0);
            o1.y = h1.y + 0.1f * tanhf(acc[mt][nt][3] + b1);
            *reinterpret_cast<float2*>(&Hout[(size_t)m0 * D_DIM + col]) = o0;
            *reinterpret_cast<float2*>(&Hout[(size_t)m1 * D_DIM + col]) = o1;
        }
    }
}

extern "C" void kernel_launch(void* const* d_in, const int* in_sizes, int n_in,
                              void* d_out, int out_size)
{
    (void)in_sizes; (void)n_in; (void)out_size;
    const float* x = (const float*)d_in[0];   // [1024, 1024]
    const float* W = (const float*)d_in[1];   // [10, 1024, 1024]
    const float* b = (const float*)d_in[2];   // [10, 1024]

    float* out  = (float*)d_out;
    const size_t BD = (size_t)D_DIM * D_DIM;
    float* feat = out;                         // [1024,1024]
    float* traj = out + BD;                    // [101,1024,1024]

    cudaFuncSetAttribute(ode_step_mma,
                         cudaFuncAttributeMaxDynamicSharedMemorySize, SMEM_BYTES);

    // traj[0] = x
    cudaMemcpyAsync(traj, x, BD * sizeof(float), cudaMemcpyDeviceToDevice, 0);

    dim3 grid(D_DIM / BN, D_DIM / BM);   // (16, 8) = 128 CTAs
    dim3 block(THREADS);

    for (int n = 0; n < 100; n++) {
        int k = n / 10;
        ode_step_mma<<<grid, block, SMEM_BYTES, 0>>>(
            traj + (size_t)n * BD,
            W + (size_t)k * BD,
            b + (size_t)k * D_DIM,
            traj + (size_t)(n + 1) * BD);
    }

    // features = traj[100]
    cudaMemcpyAsync(feat, traj + (size_t)100 * BD, BD * sizeof(float),
                    cudaMemcpyDeviceToDevice, 0);
}

// round 4
// speedup vs baseline: 2.6737x; 1.2405x over previous
#include <cuda_runtime.h>
#include <cstdint>
#include <math.h>

// NeuralODE via mma.sync m16n8k8 tf32 (legacy tensor path; tcgen05 is 'a'-gated).
// h_{n+1} = h_n + 0.1 * tanh(h_n @ W[k]^T + b[k]), k = n/10, n = 0..99, B=D=1024.
// Output: [features 1024*1024][traj 101*1024*1024]; recurrence runs in place in traj.
//
// R4: BK=64, single __syncthreads per stage, software-pipelined fragment loads,
// fast tanh. CTA 128x64, 8 warps, warp tile 32x32 (4x2 warp grid), grid=128.

#define D_DIM   1024
#define BM      128
#define BN      64
#define BK      64
#define THREADS 256
#define N_STAGES (D_DIM / BK)   // 16

// SMEM row stride in words: 68 = 64 + 4 pad; 68 mod 32 = 4 -> fragment LDS.32
// bank = (4*g + tig) mod 32, all 32 lanes distinct -> conflict-free.
#define ASTR 68
#define A_TILE (BM * ASTR)            // 8704 words
#define B_TILE (BN * ASTR)            // 4352 words
#define SMEM_BYTES (2 * (A_TILE + B_TILE) * 4)   // 104448 B

__device__ __forceinline__ uint32_t f2tf32(float f) {
    uint32_t r;
    asm("cvt.rna.tf32.f32 %0, %1;" : "=r"(r) : "f"(f));
    return r;
}

__device__ __forceinline__ void mma_tf32(float c[4],
                                         uint32_t a0, uint32_t a1,
                                         uint32_t a2, uint32_t a3,
                                         uint32_t b0, uint32_t b1) {
    asm volatile(
        "mma.sync.aligned.m16n8k8.row.col.f32.tf32.tf32.f32 "
        "{%0,%1,%2,%3}, {%4,%5,%6,%7}, {%8,%9}, {%0,%1,%2,%3};"
        : "+f"(c[0]), "+f"(c[1]), "+f"(c[2]), "+f"(c[3])
        : "r"(a0), "r"(a1), "r"(a2), "r"(a3), "r"(b0), "r"(b1));
}

__device__ __forceinline__ float fast_tanh(float x) {
    float ax = fabsf(x);
    float t = __expf(-2.0f * ax);
    float r = __fdividef(1.0f - t, 1.0f + t);
    return copysignf(r, x);
}

__global__ __launch_bounds__(THREADS, 1)
void ode_step_mma(const float* __restrict__ H,
                  const float* __restrict__ Wk,
                  const float* __restrict__ bk,
                  float* __restrict__ Hout)
{
    extern __shared__ uint32_t smem[];
    uint32_t* const Abuf[2] = { smem, smem + A_TILE };
    uint32_t* const Bbuf[2] = { smem + 2 * A_TILE, smem + 2 * A_TILE + B_TILE };

    const int tid  = threadIdx.x;
    const int wid  = tid >> 5;
    const int lane = tid & 31;
    const int g    = lane >> 2;     // 0..7
    const int tig  = lane & 3;      // 0..3
    const int wm   = wid & 3;       // warp M 0..3
    const int wn   = wid >> 2;      // warp N 0..1
    const int bm   = blockIdx.y * BM;
    const int bn   = blockIdx.x * BN;
    const int mrow = wm * 32;
    const int ncol = wn * 32;

    float4 av[8];   // A global staging: 128 rows x 16 float4 / 256 thr = 8
    float4 bv[4];   // B global staging: 64 rows x 16 float4 / 256 thr = 4

    auto load_global = [&](int s) {
        const int k0 = s * BK;
#pragma unroll
        for (int i = 0; i < 8; i++) {
            int idx = tid + i * THREADS;
            int r = idx >> 4, c4 = idx & 15;
            av[i] = *reinterpret_cast<const float4*>(
                &H[(size_t)(bm + r) * D_DIM + k0 + c4 * 4]);
        }
#pragma unroll
        for (int i = 0; i < 4; i++) {
            int idx = tid + i * THREADS;
            int r = idx >> 4, c4 = idx & 15;
            bv[i] = *reinterpret_cast<const float4*>(
                &Wk[(size_t)(bn + r) * D_DIM + k0 + c4 * 4]);
        }
    };

    auto store_smem = [&](int buf) {
#pragma unroll
        for (int i = 0; i < 8; i++) {
            int idx = tid + i * THREADS;
            int r = idx >> 4, c4 = idx & 15;
            uint4 u;
            u.x = f2tf32(av[i].x); u.y = f2tf32(av[i].y);
            u.z = f2tf32(av[i].z); u.w = f2tf32(av[i].w);
            *reinterpret_cast<uint4*>(&Abuf[buf][r * ASTR + c4 * 4]) = u;
        }
#pragma unroll
        for (int i = 0; i < 4; i++) {
            int idx = tid + i * THREADS;
            int r = idx >> 4, c4 = idx & 15;
            uint4 u;
            u.x = f2tf32(bv[i].x); u.y = f2tf32(bv[i].y);
            u.z = f2tf32(bv[i].z); u.w = f2tf32(bv[i].w);
            *reinterpret_cast<uint4*>(&Bbuf[buf][r * ASTR + c4 * 4]) = u;
        }
    };

    float acc[2][4][4];
#pragma unroll
    for (int mt = 0; mt < 2; mt++)
#pragma unroll
        for (int nt = 0; nt < 4; nt++)
#pragma unroll
            for (int r = 0; r < 4; r++) acc[mt][nt][r] = 0.0f;

    // fragment double buffers (software pipeline within a stage)
    uint32_t fa[2][8], fb[2][8];

    auto load_frag = [&](const uint32_t* __restrict__ A,
                         const uint32_t* __restrict__ B,
                         int j, int p) {
        const int ko = j * 8 + tig;
        const uint32_t* Aj = A + ko;
        const uint32_t* Bj = B + ko;
#pragma unroll
        for (int mt = 0; mt < 2; mt++) {
            const int mb = mrow + mt * 16;
            fa[p][mt * 4 + 0] = Aj[(mb + g)      * ASTR];
            fa[p][mt * 4 + 1] = Aj[(mb + g + 8)  * ASTR];
            fa[p][mt * 4 + 2] = Aj[(mb + g)      * ASTR + 4];
            fa[p][mt * 4 + 3] = Aj[(mb + g + 8)  * ASTR + 4];
        }
#pragma unroll
        for (int nt = 0; nt < 4; nt++) {
            const int nb = ncol + nt * 8;
            fb[p][nt * 2 + 0] = Bj[(nb + g) * ASTR];
            fb[p][nt * 2 + 1] = Bj[(nb + g) * ASTR + 4];
        }
    };

    auto do_mma = [&](int p) {
#pragma unroll
        for (int mt = 0; mt < 2; mt++)
#pragma unroll
            for (int nt = 0; nt < 4; nt++)
                mma_tf32(acc[mt][nt],
                         fa[p][mt * 4 + 0], fa[p][mt * 4 + 1],
                         fa[p][mt * 4 + 2], fa[p][mt * 4 + 3],
                         fb[p][nt * 2 + 0], fb[p][nt * 2 + 1]);
    };

    // ---- prologue ----
    load_global(0);
    store_smem(0);
    __syncthreads();

    for (int s = 0; s < N_STAGES; s++) {
        const int buf = s & 1;
        if (s + 1 < N_STAGES) load_global(s + 1);   // LDG overlaps compute

        const uint32_t* A = Abuf[buf];
        const uint32_t* B = Bbuf[buf];

        load_frag(A, B, 0, 0);
#pragma unroll
        for (int j = 0; j < 8; j++) {
            if (j + 1 < 8) load_frag(A, B, j + 1, (j + 1) & 1);
            do_mma(j & 1);
        }

        if (s + 1 < N_STAGES) store_smem(buf ^ 1);  // write other buffer
        __syncthreads();
    }

    // ---- fused epilogue: h + 0.1 * tanh(acc + b) ----
#pragma unroll
    for (int mt = 0; mt < 2; mt++) {
        const int m0 = bm + mrow + mt * 16 + g;
        const int m1 = m0 + 8;
#pragma unroll
        for (int nt = 0; nt < 4; nt++) {
            const int col = bn + ncol + nt * 8 + tig * 2;
            const float b0 = __ldg(&bk[col]);
            const float b1 = __ldg(&bk[col + 1]);

            float2 h0 = *reinterpret_cast<const float2*>(&H[(size_t)m0 * D_DIM + col]);
            float2 h1 = *reinterpret_cast<const float2*>(&H[(size_t)m1 * D_DIM + col]);
            float2 o0, o1;
            o0.x = h0.x + 0.1f * fast_tanh(acc[mt][nt][0] + b0);
            o0.y = h0.y + 0.1f * fast_tanh(acc[mt][nt][1] + b1);
            o1.x = h1.x + 0.1f * fast_tanh(acc[mt][nt][2] + b0);
            o1.y = h1.y + 0.1f * fast_tanh(acc[mt][nt][3] + b1);
            *reinterpret_cast<float2*>(&Hout[(size_t)m0 * D_DIM + col]) = o0;
            *reinterpret_cast<float2*>(&Hout[(size_t)m1 * D_DIM + col]) = o1;
        }
    }
}

extern "C" void kernel_launch(void* const* d_in, const int* in_sizes, int n_in,
                              void* d_out, int out_size)
{
    (void)in_sizes; (void)n_in; (void)out_size;
    const float* x = (const float*)d_in[0];   // [1024, 1024]
    const float* W = (const float*)d_in[1];   // [10, 1024, 1024]
    const float* b = (const float*)d_in[2];   // [10, 1024]

    float* out  = (float*)d_out;
    const size_t BD = (size_t)D_DIM * D_DIM;
    float* feat = out;                         // [1024,1024]
    float* traj = out + BD;                    // [101,1024,1024]

    cudaFuncSetAttribute(ode_step_mma,
                         cudaFuncAttributeMaxDynamicSharedMemorySize, SMEM_BYTES);

    // traj[0] = x
    cudaMemcpyAsync(traj, x, BD * sizeof(float), cudaMemcpyDeviceToDevice, 0);

    dim3 grid(D_DIM / BN, D_DIM / BM);   // (16, 8) = 128 CTAs
    dim3 block(THREADS);

    for (int n = 0; n < 100; n++) {
        int k = n / 10;
        ode_step_mma<<<grid, block, SMEM_BYTES, 0>>>(
            traj + (size_t)n * BD,
            W + (size_t)k * BD,
            b + (size_t)k * D_DIM,
            traj + (size_t)(n + 1) * BD);
    }

    // features = traj[100]
    cudaMemcpyAsync(feat, traj + (size_t)100 * BD, BD * sizeof(float),
                    cudaMemcpyDeviceToDevice, 0);
}

// round 5
// speedup vs baseline: 3.7358x; 1.3973x over previous
#include <cuda_runtime.h>
#include <cstdint>
#include <math.h>

// NeuralODE via mma.sync m16n8k8 tf32 + cp.async multistage pipeline.
// h_{n+1} = h_n + 0.1 * tanh(h_n @ W[k]^T + b[k]), k = n/10, n = 0..99, B=D=1024.
// Output: [features 1024*1024][traj 101*1024*1024]; fp32 recurrence in traj.
// tf32 operands pre-converted: W once per launch, H by the previous step's epilogue.

#define D_DIM   1024
#define BM      128
#define BN      64
#define BK      64
#define THREADS 256
#define KITERS  (D_DIM / BK)    // 16
#define STAGES  4

// SMEM row stride in words: 68 -> fragment LDS bank = (4g + tig) mod 32, conflict-free.
#define ASTR 68
#define A_WORDS (BM * ASTR)                 // 8704
#define B_WORDS (BN * ASTR)                 // 4352
#define STAGE_WORDS (A_WORDS + B_WORDS)     // 13056
#define SMEM_BYTES (STAGES * STAGE_WORDS * 4)   // 208896

// Static scratch (allowed: __device__ globals, no runtime allocation)
__device__ uint32_t g_Wtf[10u * 1024u * 1024u];     // W in tf32 bits
__device__ uint32_t g_Htf[2][1024u * 1024u];        // H ping-pong in tf32 bits

__device__ __forceinline__ uint32_t f2tf32(float f) {
    uint32_t r;
    asm("cvt.rna.tf32.f32 %0, %1;" : "=r"(r) : "f"(f));
    return r;
}

__device__ __forceinline__ void mma_tf32(float c[4],
                                         uint32_t a0, uint32_t a1,
                                         uint32_t a2, uint32_t a3,
                                         uint32_t b0, uint32_t b1) {
    asm volatile(
        "mma.sync.aligned.m16n8k8.row.col.f32.tf32.tf32.f32 "
        "{%0,%1,%2,%3}, {%4,%5,%6,%7}, {%8,%9}, {%0,%1,%2,%3};"
        : "+f"(c[0]), "+f"(c[1]), "+f"(c[2]), "+f"(c[3])
        : "r"(a0), "r"(a1), "r"(a2), "r"(a3), "r"(b0), "r"(b1));
}

__device__ __forceinline__ float fast_tanh(float x) {
    float ax = fabsf(x);
    float t = __expf(-2.0f * ax);
    float r = __fdividef(1.0f - t, 1.0f + t);
    return copysignf(r, x);
}

__device__ __forceinline__ uint32_t smem_u32(const void* p) {
    uint32_t a;
    asm("{ .reg .u64 t; cvta.to.shared.u64 t, %1; cvt.u32.u64 %0, t; }"
        : "=r"(a) : "l"(p));
    return a;
}

#define CP_ASYNC(dst, src) \
    asm volatile("cp.async.cg.shared.global [%0], [%1], 16;" \
                 :: "r"(dst), "l"(src) : "memory")
#define CP_COMMIT() asm volatile("cp.async.commit_group;" ::: "memory")
#define CP_WAIT2()  asm volatile("cp.async.wait_group 2;" ::: "memory")

__global__ void convert_tf32(const float4* __restrict__ in,
                             uint4* __restrict__ out, int n4)
{
    for (int i = blockIdx.x * blockDim.x + threadIdx.x; i < n4;
         i += gridDim.x * blockDim.x) {
        float4 v = in[i];
        uint4 u;
        u.x = f2tf32(v.x); u.y = f2tf32(v.y);
        u.z = f2tf32(v.z); u.w = f2tf32(v.w);
        out[i] = u;
    }
}

__global__ __launch_bounds__(THREADS, 1)
void ode_step(const uint32_t* __restrict__ Atf,   // H tf32 bits [1024,1024]
              const uint32_t* __restrict__ Btf,   // W slab tf32 bits [1024,1024]
              const float*    __restrict__ Hfp,   // traj[n] fp32
              const float*    __restrict__ bk,
              float*          __restrict__ Hout,  // traj[n+1] fp32
              uint32_t*       __restrict__ Houttf)// Htf[(n+1)&1]
{
    extern __shared__ uint32_t smem[];
    const uint32_t sbase = smem_u32(smem);

    const int tid  = threadIdx.x;
    const int wid  = tid >> 5;
    const int lane = tid & 31;
    const int g    = lane >> 2;
    const int tig  = lane & 3;
    const int wm   = wid & 3;
    const int wn   = wid >> 2;
    const int bm   = blockIdx.y * BM;
    const int bn   = blockIdx.x * BN;
    const int mrow = wm * 32;
    const int ncol = wn * 32;

    auto issue_stage = [&](int s) {
        const int slot = s & (STAGES - 1);
        const uint32_t abase = sbase + (uint32_t)(slot * STAGE_WORDS) * 4u;
        const uint32_t bbase = abase + (uint32_t)A_WORDS * 4u;
        const int k0 = s * BK;
#pragma unroll
        for (int i = 0; i < 8; i++) {
            int idx = tid + i * THREADS;
            int r = idx >> 4, q = idx & 15;
            CP_ASYNC(abase + (uint32_t)(r * ASTR + q * 4) * 4u,
                     Atf + (size_t)(bm + r) * D_DIM + k0 + q * 4);
        }
#pragma unroll
        for (int i = 0; i < 4; i++) {
            int idx = tid + i * THREADS;
            int r = idx >> 4, q = idx & 15;
            CP_ASYNC(bbase + (uint32_t)(r * ASTR + q * 4) * 4u,
                     Btf + (size_t)(bn + r) * D_DIM + k0 + q * 4);
        }
        CP_COMMIT();
    };

    float acc[2][4][4];
#pragma unroll
    for (int mt = 0; mt < 2; mt++)
#pragma unroll
        for (int nt = 0; nt < 4; nt++)
#pragma unroll
            for (int r = 0; r < 4; r++) acc[mt][nt][r] = 0.0f;

    uint32_t fa[2][8], fb[2][8];

    auto load_frag = [&](const uint32_t* __restrict__ A,
                         const uint32_t* __restrict__ B,
                         int j, int p) {
        const int ko = j * 8 + tig;
        const uint32_t* Aj = A + ko;
        const uint32_t* Bj = B + ko;
#pragma unroll
        for (int mt = 0; mt < 2; mt++) {
            const int mb = mrow + mt * 16;
            fa[p][mt * 4 + 0] = Aj[(mb + g)     * ASTR];
            fa[p][mt * 4 + 1] = Aj[(mb + g + 8) * ASTR];
            fa[p][mt * 4 + 2] = Aj[(mb + g)     * ASTR + 4];
            fa[p][mt * 4 + 3] = Aj[(mb + g + 8) * ASTR + 4];
        }
#pragma unroll
        for (int nt = 0; nt < 4; nt++) {
            const int nb = ncol + nt * 8;
            fb[p][nt * 2 + 0] = Bj[(nb + g) * ASTR];
            fb[p][nt * 2 + 1] = Bj[(nb + g) * ASTR + 4];
        }
    };

    auto do_mma = [&](int p) {
#pragma unroll
        for (int mt = 0; mt < 2; mt++)
#pragma unroll
            for (int nt = 0; nt < 4; nt++)
                mma_tf32(acc[mt][nt],
                         fa[p][mt * 4 + 0], fa[p][mt * 4 + 1],
                         fa[p][mt * 4 + 2], fa[p][mt * 4 + 3],
                         fb[p][nt * 2 + 0], fb[p][nt * 2 + 1]);
    };

    // ---- prologue: prefetch 3 stages ----
    issue_stage(0);
    issue_stage(1);
    issue_stage(2);

    for (int s = 0; s < KITERS; s++) {
        CP_WAIT2();            // this thread's group s complete
        __syncthreads();       // -> stage s complete block-wide

        if (s + 3 < KITERS) issue_stage(s + 3);
        else CP_COMMIT();      // keep group numbering uniform

        const uint32_t* A = smem + (s & (STAGES - 1)) * STAGE_WORDS;
        const uint32_t* B = A + A_WORDS;

        load_frag(A, B, 0, 0);
#pragma unroll
        for (int j = 0; j < 8; j++) {
            if (j + 1 < 8) load_frag(A, B, j + 1, (j + 1) & 1);
            do_mma(j & 1);
        }
    }

    // ---- fused epilogue: h + 0.1 * tanh(acc + b); also emit tf32 copy ----
#pragma unroll
    for (int mt = 0; mt < 2; mt++) {
        const int m0 = bm + mrow + mt * 16 + g;
        const int m1 = m0 + 8;
#pragma unroll
        for (int nt = 0; nt < 4; nt++) {
            const int col = bn + ncol + nt * 8 + tig * 2;
            const float b0 = __ldg(&bk[col]);
            const float b1 = __ldg(&bk[col + 1]);

            float2 h0 = *reinterpret_cast<const float2*>(&Hfp[(size_t)m0 * D_DIM + col]);
            float2 h1 = *reinterpret_cast<const float2*>(&Hfp[(size_t)m1 * D_DIM + col]);
            float2 o0, o1;
            o0.x = h0.x + 0.1f * fast_tanh(acc[mt][nt][0] + b0);
            o0.y = h0.y + 0.1f * fast_tanh(acc[mt][nt][1] + b1);
            o1.x = h1.x + 0.1f * fast_tanh(acc[mt][nt][2] + b0);
            o1.y = h1.y + 0.1f * fast_tanh(acc[mt][nt][3] + b1);
            *reinterpret_cast<float2*>(&Hout[(size_t)m0 * D_DIM + col]) = o0;
            *reinterpret_cast<float2*>(&Hout[(size_t)m1 * D_DIM + col]) = o1;

            uint2 t0, t1;
            t0.x = f2tf32(o0.x); t0.y = f2tf32(o0.y);
            t1.x = f2tf32(o1.x); t1.y = f2tf32(o1.y);
            *reinterpret_cast<uint2*>(&Houttf[(size_t)m0 * D_DIM + col]) = t0;
            *reinterpret_cast<uint2*>(&Houttf[(size_t)m1 * D_DIM + col]) = t1;
        }
    }
}

extern "C" void kernel_launch(void* const* d_in, const int* in_sizes, int n_in,
                              void* d_out, int out_size)
{
    (void)in_sizes; (void)n_in; (void)out_size;
    const float* x = (const float*)d_in[0];   // [1024, 1024]
    const float* W = (const float*)d_in[1];   // [10, 1024, 1024]
    const float* b = (const float*)d_in[2];   // [10, 1024]

    float* out  = (float*)d_out;
    const size_t BD = (size_t)D_DIM * D_DIM;
    float* feat = out;
    float* traj = out + BD;

    uint32_t *wtf = nullptr, *htf = nullptr;
    cudaGetSymbolAddress((void**)&wtf, g_Wtf);
    cudaGetSymbolAddress((void**)&htf, g_Htf);
    uint32_t* htf0 = htf;
    uint32_t* htf1 = htf + BD;

    cudaFuncSetAttribute(ode_step,
                         cudaFuncAttributeMaxDynamicSharedMemorySize, SMEM_BYTES);

    // Pre-convert W (all 10 slabs) and x to tf32 bits; traj[0] = x.
    convert_tf32<<<4096, 256>>>((const float4*)W, (uint4*)wtf,
                                (int)(10 * BD / 4));
    convert_tf32<<<1024, 256>>>((const float4*)x, (uint4*)htf0,
                                (int)(BD / 4));
    cudaMemcpyAsync(traj, x, BD * sizeof(float), cudaMemcpyDeviceToDevice, 0);

    dim3 grid(D_DIM / BN, D_DIM / BM);   // (16, 8) = 128 CTAs
    dim3 block(THREADS);

    for (int n = 0; n < 100; n++) {
        int k = n / 10;
        uint32_t* hin  = (n & 1) ? htf1 : htf0;
        uint32_t* hnew = (n & 1) ? htf0 : htf1;
        ode_step<<<grid, block, SMEM_BYTES, 0>>>(
            hin,
            wtf + (size_t)k * BD,
            traj + (size_t)n * BD,
            b + (size_t)k * D_DIM,
            traj + (size_t)(n + 1) * BD,
            hnew);
    }

    cudaMemcpyAsync(feat, traj + (size_t)100 * BD, BD * sizeof(float),
                    cudaMemcpyDeviceToDevice, 0);
}